// round 9
// baseline (speedup 1.0000x reference)
#include <cuda_runtime.h>
#include <cstdint>
#include <math.h>

#define BATCH   8
#define NNODES  2048
#define FDIM    256
#define HEADS   4
#define HD      256
#define MTOT    (BATCH*NNODES)

// ---- scratch ----
__device__ float g_Wh[(size_t)MTOT * HD];   // Wh, tf32-rounded, natural [node][feat]
__device__ float g_e[MTOT * HEADS];
__device__ float g_att[MTOT];

// ================= helpers =================
__device__ __forceinline__ uint32_t smem_u32(const void* p) {
    uint32_t a;
    asm("{ .reg .u64 t; cvta.to.shared.u64 t, %1; cvt.u32.u64 %0, t; }" : "=r"(a) : "l"(p));
    return a;
}
__device__ __forceinline__ float tf32_rna(float x) {
    uint32_t u;
    asm("cvt.rna.tf32.f32 %0, %1;" : "=r"(u) : "f"(x));
    return __uint_as_float(u);
}

#define MMA1688(c, a, b0, b1) \
    asm volatile("mma.sync.aligned.m16n8k8.row.col.f32.tf32.tf32.f32 " \
        "{%0,%1,%2,%3}, {%4,%5,%6,%7}, {%8,%9}, {%0,%1,%2,%3};" \
        : "+f"((c)[0]), "+f"((c)[1]), "+f"((c)[2]), "+f"((c)[3]) \
        : "r"((a)[0]), "r"((a)[1]), "r"((a)[2]), "r"((a)[3]), "r"(b0), "r"(b1))

#define CPASYNC16(dst, src) \
    asm volatile("cp.async.ca.shared.global [%0], [%1], 16;" :: "r"(dst), "l"(src))
#define CPCOMMIT() asm volatile("cp.async.commit_group;")
#define CPWAIT0()  asm volatile("cp.async.wait_group 0;")

// ============================================================
// Kernel A: Wh = X @ W (fp32 SIMT, exact for e)
// BM=128, BN=64, BK=16, 256 threads, 8x4 microtile
// Xs row-major [row][k] -> a-operand scalar LDS is 2-address broadcast
// ============================================================
__global__ __launch_bounds__(256) void k_wh(const float* __restrict__ X,
                                            const float* __restrict__ W) {
    __shared__ float Xs[128][20];
    __shared__ float Bs[16][68];
    __shared__ float esh[128][17];

    const int t    = threadIdx.x;
    const int m0   = blockIdx.y * 128;
    const int n0   = blockIdx.x * 64;
    const int trow = t >> 4;          // 0..15 -> rows trow*8..+7
    const int tcol = t & 15;          // cols tcol*4..+3

    float acc[8][4] = {};

    for (int k0 = 0; k0 < FDIM; k0 += 16) {
        #pragma unroll
        for (int it = 0; it < 2; it++) {          // X tile: 512 float4
            int idx = t + it * 256;
            int row = idx >> 2, q = idx & 3;
            float4 v = *(const float4*)(X + (size_t)(m0 + row) * FDIM + k0 + q * 4);
            *(float4*)&Xs[row][q * 4] = v;
        }
        {                                         // W tile: 256 float4
            int k = t >> 4, j4 = (t & 15) << 2;
            *(float4*)&Bs[k][j4] = *(const float4*)(W + (size_t)(k0 + k) * HD + n0 + j4);
        }
        __syncthreads();
        #pragma unroll
        for (int k = 0; k < 16; k++) {
            float4 b4 = *(const float4*)&Bs[k][tcol * 4];
            float b[4] = {b4.x, b4.y, b4.z, b4.w};
            float a[8];
            #pragma unroll
            for (int i = 0; i < 8; i++) a[i] = Xs[trow * 8 + i][k];
            #pragma unroll
            for (int i = 0; i < 8; i++)
                #pragma unroll
                for (int j = 0; j < 4; j++)
                    acc[i][j] = fmaf(a[i], b[j], acc[i][j]);
        }
        __syncthreads();
    }

    // coalesced tf32-rounded write
    #pragma unroll
    for (int i = 0; i < 8; i++) {
        int m = m0 + trow * 8 + i;
        float4 o;
        o.x = tf32_rna(acc[i][0]); o.y = tf32_rna(acc[i][1]);
        o.z = tf32_rna(acc[i][2]); o.w = tf32_rna(acc[i][3]);
        *(float4*)(g_Wh + (size_t)m * HD + n0 + tcol * 4) = o;
    }

    #pragma unroll
    for (int i = 0; i < 8; i++) {
        float s = acc[i][0]*acc[i][0] + acc[i][1]*acc[i][1]
                + acc[i][2]*acc[i][2] + acc[i][3]*acc[i][3];
        esh[trow * 8 + i][tcol] = s;
    }
    __syncthreads();
    if (t < 128) {
        float s = 0.f;
        #pragma unroll
        for (int j = 0; j < 16; j++) s += esh[t][j];
        g_e[(size_t)(m0 + t) * HEADS + (n0 >> 6)] = s;
    }
}

// ============================================================
// Kernel B: fused softmax stats + head-mean attention (one block / batch)
// ============================================================
__global__ __launch_bounds__(256) void k_soft_att() {
    const int b = blockIdx.x;
    const int t = threadIdx.x;
    __shared__ float red[256];
    __shared__ float s_mx[HEADS], s_inv[HEADS];

    const float* eb = g_e + (size_t)b * NNODES * HEADS;

    for (int h = 0; h < HEADS; h++) {
        float mx = -1e30f;
        for (int n = t; n < NNODES; n += 256)
            mx = fmaxf(mx, eb[n * HEADS + h]);
        red[t] = mx; __syncthreads();
        for (int s = 128; s > 0; s >>= 1) {
            if (t < s) red[t] = fmaxf(red[t], red[t + s]);
            __syncthreads();
        }
        mx = red[0]; __syncthreads();

        float sum = 0.f;
        for (int n = t; n < NNODES; n += 256)
            sum += __expf(eb[n * HEADS + h] - mx);
        red[t] = sum; __syncthreads();
        for (int s = 128; s > 0; s >>= 1) {
            if (t < s) red[t] += red[t + s];
            __syncthreads();
        }
        if (t == 0) { s_mx[h] = mx; s_inv[h] = 1.0f / red[0]; }
        __syncthreads();
    }

    for (int n = t; n < NNODES; n += 256) {
        float a = 0.f;
        #pragma unroll
        for (int h = 0; h < HEADS; h++)
            a += __expf(eb[n * HEADS + h] - s_mx[h]) * s_inv[h];
        g_att[b * NNODES + n] = 0.25f * a;
    }
}

// ============================================================
// Kernel C: single-pass tf32 mma.sync GEMM
//   out = relu(att*(adj @ Wh) + bias)
// BM=64, BN=64, BK=32, 4 warps (2m x 2n), 128 threads, double-buffered
// 1024 CTAs -> fine-grained load balance (6.9 CTAs/SM)
// A tile [64][36] f32 (conflict-free), B tile [32][72] f32 (conflict-free)
// ============================================================
#define A_LD   36
#define B_LD   72
#define B_OFF  9216                  // 64*36*4
#define STAGE  18432                 // 9216 + 32*72*4

__global__ void __launch_bounds__(128)
k_out_tf32(const float* __restrict__ adj, const float* __restrict__ bias,
           float* __restrict__ out) {
    extern __shared__ char smem[];
    const uint32_t sb = smem_u32(smem);
    const int t    = threadIdx.x;
    const int lane = t & 31;
    const int wid  = t >> 5;
    const int b    = blockIdx.z;
    const int n0   = blockIdx.x * 64;    // n fastest -> adj tile L2 reuse
    const int m0   = blockIdx.y * 64;
    const int warp_m = wid & 1;          // 32 rows
    const int warp_n = wid >> 1;         // 32 cols

    const float* adjb = adj + (size_t)b * NNODES * NNODES;
    const float* Whb  = g_Wh + ((size_t)b * NNODES) * HD;

    float c[2][4][4];
    #pragma unroll
    for (int mt = 0; mt < 2; mt++)
        #pragma unroll
        for (int nt = 0; nt < 4; nt++)
            #pragma unroll
            for (int j = 0; j < 4; j++) c[mt][nt][j] = 0.f;

    // ---- stage loader (128 threads) ----
    auto load_stage = [&](int k0, uint32_t dst) {
        #pragma unroll
        for (int it = 0; it < 4; it++) {        // A: 64x32 = 512 chunks of 16B
            int idx = t + it * 128;
            int row = idx >> 3, u = idx & 7;
            CPASYNC16(dst + row * (A_LD*4) + u * 16,
                      adjb + (size_t)(m0 + row) * NNODES + k0 + u * 4);
        }
        #pragma unroll
        for (int it = 0; it < 4; it++) {        // B: 32x64 = 512 chunks of 16B
            int idx = t + it * 128;
            int row = idx >> 4, u = idx & 15;
            CPASYNC16(dst + B_OFF + row * (B_LD*4) + u * 16,
                      Whb + (size_t)(k0 + row) * HD + n0 + u * 4);
        }
        CPCOMMIT();
    };

    // ---- prologue ----
    load_stage(0, sb);
    CPWAIT0();
    __syncthreads();

    // ---- main loop over 64 k-tiles ----
    for (int i = 0; i < 64; i++) {
        const uint32_t cur = (uint32_t)(i & 1) * STAGE;
        if (i < 63) load_stage((i + 1) * 32, sb + (uint32_t)((i + 1) & 1) * STAGE);

        const float* Asm = (const float*)(smem + cur);
        const float* Bsm = (const float*)(smem + cur + B_OFF);

        #pragma unroll
        for (int s = 0; s < 4; s++) {
            const int kk = s * 8 + (lane & 3);
            uint32_t a[2][4];
            #pragma unroll
            for (int mt = 0; mt < 2; mt++) {
                int r = warp_m * 32 + mt * 16 + (lane >> 2);
                a[mt][0] = __float_as_uint(Asm[r * A_LD + kk]);        // raw bits: HW tf32 trunc
                a[mt][1] = __float_as_uint(Asm[(r + 8) * A_LD + kk]);
                a[mt][2] = __float_as_uint(Asm[r * A_LD + kk + 4]);
                a[mt][3] = __float_as_uint(Asm[(r + 8) * A_LD + kk + 4]);
            }
            #pragma unroll
            for (int ng = 0; ng < 4; ng++) {
                int n = warp_n * 32 + ng * 8 + (lane >> 2);
                uint32_t b0 = __float_as_uint(Bsm[kk * B_LD + n]);     // pre-rounded (RNA)
                uint32_t b1 = __float_as_uint(Bsm[(kk + 4) * B_LD + n]);
                MMA1688(c[0][ng], a[0], b0, b1);
                MMA1688(c[1][ng], a[1], b0, b1);
            }
        }

        if (i < 63) { CPWAIT0(); __syncthreads(); }
    }

    // ---- epilogue ----
    #pragma unroll
    for (int mt = 0; mt < 2; mt++) {
        int r0 = m0 + warp_m * 32 + mt * 16 + (lane >> 2);
        float att0 = g_att[b * NNODES + r0];
        float att1 = g_att[b * NNODES + r0 + 8];
        float* o0 = out + ((size_t)(b * NNODES + r0)) * HD;
        float* o1 = o0 + (size_t)8 * HD;
        #pragma unroll
        for (int nt = 0; nt < 4; nt++) {
            int col = n0 + warp_n * 32 + nt * 8 + 2 * (lane & 3);
            float2 bv = *(const float2*)(bias + col);
            float2 v0, v1;
            v0.x = fmaxf(fmaf(att0, c[mt][nt][0], bv.x), 0.f);
            v0.y = fmaxf(fmaf(att0, c[mt][nt][1], bv.y), 0.f);
            v1.x = fmaxf(fmaf(att1, c[mt][nt][2], bv.x), 0.f);
            v1.y = fmaxf(fmaf(att1, c[mt][nt][3], bv.y), 0.f);
            *(float2*)(o0 + col) = v0;
            *(float2*)(o1 + col) = v1;
        }
    }
}

// ============================================================
extern "C" void kernel_launch(void* const* d_in, const int* in_sizes, int n_in,
                              void* d_out, int out_size) {
    const float* features = (const float*)d_in[0];   // [8,2048,256]
    const float* adj      = (const float*)d_in[1];   // [8,2048,2048]
    const float* W        = (const float*)d_in[2];   // [256,256]
    const float* bias     = (const float*)d_in[3];   // [256]
    float* out = (float*)d_out;                      // [8,2048,256]

    cudaFuncSetAttribute(k_out_tf32, cudaFuncAttributeMaxDynamicSharedMemorySize, 2 * STAGE);

    k_wh      <<<dim3(HD/64, MTOT/128), 256>>>(features, W);
    k_soft_att<<<BATCH, 256>>>();
    k_out_tf32<<<dim3(HD/64, NNODES/64, BATCH), 128, 2 * STAGE>>>(adj, bias, out);
}

// round 10
// speedup vs baseline: 1.1056x; 1.1056x over previous
#include <cuda_runtime.h>
#include <cstdint>
#include <math.h>

#define BATCH   8
#define NNODES  2048
#define FDIM    256
#define HEADS   4
#define HD      256
#define MTOT    (BATCH*NNODES)

// ---- scratch ----
__device__ float g_Wh[(size_t)MTOT * HD];   // Wh, tf32-rounded, natural [node][feat]
__device__ float g_e[MTOT * HEADS];
__device__ float g_att[MTOT];

// ================= helpers =================
__device__ __forceinline__ uint32_t smem_u32(const void* p) {
    uint32_t a;
    asm("{ .reg .u64 t; cvta.to.shared.u64 t, %1; cvt.u32.u64 %0, t; }" : "=r"(a) : "l"(p));
    return a;
}
__device__ __forceinline__ float tf32_rna(float x) {
    uint32_t u;
    asm("cvt.rna.tf32.f32 %0, %1;" : "=r"(u) : "f"(x));
    return __uint_as_float(u);
}

#define MMA1688(c, a, b0, b1) \
    asm volatile("mma.sync.aligned.m16n8k8.row.col.f32.tf32.tf32.f32 " \
        "{%0,%1,%2,%3}, {%4,%5,%6,%7}, {%8,%9}, {%0,%1,%2,%3};" \
        : "+f"((c)[0]), "+f"((c)[1]), "+f"((c)[2]), "+f"((c)[3]) \
        : "r"((a)[0]), "r"((a)[1]), "r"((a)[2]), "r"((a)[3]), "r"(b0), "r"(b1))

#define CPASYNC16(dst, src) \
    asm volatile("cp.async.ca.shared.global [%0], [%1], 16;" :: "r"(dst), "l"(src))
#define CPCOMMIT() asm volatile("cp.async.commit_group;")
#define CPWAIT0()  asm volatile("cp.async.wait_group 0;")

// ============================================================
// Kernel A: Wh = X @ W (fp32 SIMT, exact for e); double-buffered stages.
// BM=64, BN=64, BK=16, 256 threads, 4x4 microtile (R7-proven body).
// X: LDG prefetch -> STS transpose (k-major As). W: cp.async.
// ============================================================
__global__ __launch_bounds__(256) void k_wh(const float* __restrict__ X,
                                            const float* __restrict__ W) {
    __shared__ float As[2][16][68];
    __shared__ float Bs[2][16][68];
    __shared__ float esh[64][17];

    const int t    = threadIdx.x;
    const int m0   = blockIdx.y * 64;
    const int n0   = blockIdx.x * 64;
    const int trow = t >> 4;
    const int tcol = t & 15;

    // loader mapping
    const int xi = t >> 2;          // row 0..63
    const int xq = t & 3;           // k-quad
    const int wk = t >> 4;          // 0..15
    const int wj = (t & 15) << 2;   // col*4

    float acc[4][4] = {};

    auto ldgX = [&](int k0) -> float4 {
        return *(const float4*)(X + (size_t)(m0 + xi) * FDIM + k0 + xq * 4);
    };
    auto stsX = [&](float4 v, int s) {
        As[s][xq*4+0][xi] = v.x; As[s][xq*4+1][xi] = v.y;
        As[s][xq*4+2][xi] = v.z; As[s][xq*4+3][xi] = v.w;
    };
    auto cpB = [&](int k0, int s) {
        CPASYNC16(smem_u32(&Bs[s][wk][wj]), W + (size_t)(k0 + wk) * HD + n0 + wj);
        CPCOMMIT();
    };

    // ---- prologue ----
    {
        float4 v0 = ldgX(0);
        cpB(0, 0);
        stsX(v0, 0);
        CPWAIT0();
        __syncthreads();
    }

    // ---- main loop: 16 k-tiles, double-buffered ----
    for (int kt = 0; kt < 16; kt++) {
        const int cur = kt & 1;
        float4 nv;
        if (kt < 15) { nv = ldgX((kt + 1) * 16); cpB((kt + 1) * 16, cur ^ 1); }

        #pragma unroll
        for (int k = 0; k < 16; k++) {
            float a[4], b[4];
            #pragma unroll
            for (int i = 0; i < 4; i++) a[i] = As[cur][k][trow*4 + i];
            #pragma unroll
            for (int j = 0; j < 4; j++) b[j] = Bs[cur][k][tcol*4 + j];
            #pragma unroll
            for (int i = 0; i < 4; i++)
                #pragma unroll
                for (int j = 0; j < 4; j++)
                    acc[i][j] = fmaf(a[i], b[j], acc[i][j]);
        }
        __syncthreads();                        // readers done before next overwrite of 'cur'
        if (kt < 15) {
            stsX(nv, cur ^ 1);
            CPWAIT0();
            __syncthreads();                    // stage cur^1 fully visible
        }
    }

    // coalesced natural-layout write, tf32-rounded
    #pragma unroll
    for (int i = 0; i < 4; i++) {
        int m = m0 + trow * 4 + i;
        float4 o;
        o.x = tf32_rna(acc[i][0]); o.y = tf32_rna(acc[i][1]);
        o.z = tf32_rna(acc[i][2]); o.w = tf32_rna(acc[i][3]);
        *(float4*)(g_Wh + (size_t)m * HD + n0 + tcol * 4) = o;
    }

    #pragma unroll
    for (int i = 0; i < 4; i++) {
        float s = acc[i][0]*acc[i][0] + acc[i][1]*acc[i][1]
                + acc[i][2]*acc[i][2] + acc[i][3]*acc[i][3];
        esh[trow*4 + i][tcol] = s;
    }
    __syncthreads();
    if (t < 64) {
        float s = 0.f;
        #pragma unroll
        for (int j = 0; j < 16; j++) s += esh[t][j];
        g_e[(size_t)(m0 + t) * HEADS + (n0 >> 6)] = s;
    }
}

// ============================================================
// Kernel B: fused softmax stats + head-mean attention (one block / batch)
// ============================================================
__global__ __launch_bounds__(256) void k_soft_att() {
    const int b = blockIdx.x;
    const int t = threadIdx.x;
    __shared__ float red[256];
    __shared__ float s_mx[HEADS], s_inv[HEADS];

    const float* eb = g_e + (size_t)b * NNODES * HEADS;

    for (int h = 0; h < HEADS; h++) {
        float mx = -1e30f;
        for (int n = t; n < NNODES; n += 256)
            mx = fmaxf(mx, eb[n * HEADS + h]);
        red[t] = mx; __syncthreads();
        for (int s = 128; s > 0; s >>= 1) {
            if (t < s) red[t] = fmaxf(red[t], red[t + s]);
            __syncthreads();
        }
        mx = red[0]; __syncthreads();

        float sum = 0.f;
        for (int n = t; n < NNODES; n += 256)
            sum += __expf(eb[n * HEADS + h] - mx);
        red[t] = sum; __syncthreads();
        for (int s = 128; s > 0; s >>= 1) {
            if (t < s) red[t] += red[t + s];
            __syncthreads();
        }
        if (t == 0) { s_mx[h] = mx; s_inv[h] = 1.0f / red[0]; }
        __syncthreads();
    }

    for (int n = t; n < NNODES; n += 256) {
        float a = 0.f;
        #pragma unroll
        for (int h = 0; h < HEADS; h++)
            a += __expf(eb[n * HEADS + h] - s_mx[h]) * s_inv[h];
        g_att[b * NNODES + n] = 0.25f * a;
    }
}

// ============================================================
// Kernel C: single-pass tf32 mma.sync GEMM  (EXACT R8 configuration)
//   out = relu(att*(adj @ Wh) + bias)
// BM=128, BN=64, BK=32, 8 warps (4m x 2n), double-buffered cp.async
// A fed as raw fp32 bits (HW tf32 truncation) -> no per-fragment cvt
// A tile [128][36] f32 (conflict-free), B tile [32][72] f32 (conflict-free)
// ============================================================
#define A_LD   36
#define B_LD   72
#define B_OFF  18432                 // 128*36*4
#define STAGE  27648                 // 18432 + 32*72*4

__global__ void __launch_bounds__(256)
k_out_tf32(const float* __restrict__ adj, const float* __restrict__ bias,
           float* __restrict__ out) {
    extern __shared__ char smem[];
    const uint32_t sb = smem_u32(smem);
    const int t    = threadIdx.x;
    const int lane = t & 31;
    const int wid  = t >> 5;
    const int b    = blockIdx.z;
    const int n0   = blockIdx.x * 64;    // n fastest -> adj tile L2 reuse
    const int m0   = blockIdx.y * 128;
    const int warp_m = wid & 3;          // 32 rows
    const int warp_n = wid >> 2;         // 32 cols

    const float* adjb = adj + (size_t)b * NNODES * NNODES;
    const float* Whb  = g_Wh + ((size_t)b * NNODES) * HD;

    float c[2][4][4];
    #pragma unroll
    for (int mt = 0; mt < 2; mt++)
        #pragma unroll
        for (int nt = 0; nt < 4; nt++)
            #pragma unroll
            for (int j = 0; j < 4; j++) c[mt][nt][j] = 0.f;

    // ---- stage loader ----
    auto load_stage = [&](int k0, uint32_t dst) {
        #pragma unroll
        for (int it = 0; it < 4; it++) {        // A: 1024 chunks of 16B
            int idx = t + it * 256;
            int row = idx >> 3, u = idx & 7;
            CPASYNC16(dst + row * (A_LD*4) + u * 16,
                      adjb + (size_t)(m0 + row) * NNODES + k0 + u * 4);
        }
        #pragma unroll
        for (int it = 0; it < 2; it++) {        // B: 512 chunks of 16B
            int idx = t + it * 256;
            int row = idx >> 4, u = idx & 15;
            CPASYNC16(dst + B_OFF + row * (B_LD*4) + u * 16,
                      Whb + (size_t)(k0 + row) * HD + n0 + u * 4);
        }
        CPCOMMIT();
    };

    // ---- prologue ----
    load_stage(0, sb);
    CPWAIT0();
    __syncthreads();

    // ---- main loop over 64 k-tiles ----
    for (int i = 0; i < 64; i++) {
        const uint32_t cur = (uint32_t)(i & 1) * STAGE;
        if (i < 63) load_stage((i + 1) * 32, sb + (uint32_t)((i + 1) & 1) * STAGE);

        const float* Asm = (const float*)(smem + cur);
        const float* Bsm = (const float*)(smem + cur + B_OFF);

        #pragma unroll
        for (int s = 0; s < 4; s++) {
            const int kk = s * 8 + (lane & 3);
            uint32_t a[2][4];
            #pragma unroll
            for (int mt = 0; mt < 2; mt++) {
                int r = warp_m * 32 + mt * 16 + (lane >> 2);
                a[mt][0] = __float_as_uint(Asm[r * A_LD + kk]);        // raw bits: HW tf32 trunc
                a[mt][1] = __float_as_uint(Asm[(r + 8) * A_LD + kk]);
                a[mt][2] = __float_as_uint(Asm[r * A_LD + kk + 4]);
                a[mt][3] = __float_as_uint(Asm[(r + 8) * A_LD + kk + 4]);
            }
            #pragma unroll
            for (int ng = 0; ng < 4; ng++) {
                int n = warp_n * 32 + ng * 8 + (lane >> 2);
                uint32_t b0 = __float_as_uint(Bsm[kk * B_LD + n]);     // pre-rounded (RNA)
                uint32_t b1 = __float_as_uint(Bsm[(kk + 4) * B_LD + n]);
                MMA1688(c[0][ng], a[0], b0, b1);
                MMA1688(c[1][ng], a[1], b0, b1);
            }
        }

        if (i < 63) { CPWAIT0(); __syncthreads(); }
    }

    // ---- epilogue ----
    #pragma unroll
    for (int mt = 0; mt < 2; mt++) {
        int r0 = m0 + warp_m * 32 + mt * 16 + (lane >> 2);
        float att0 = g_att[b * NNODES + r0];
        float att1 = g_att[b * NNODES + r0 + 8];
        float* o0 = out + ((size_t)(b * NNODES + r0)) * HD;
        float* o1 = o0 + (size_t)8 * HD;
        #pragma unroll
        for (int nt = 0; nt < 4; nt++) {
            int col = n0 + warp_n * 32 + nt * 8 + 2 * (lane & 3);
            float2 bv = *(const float2*)(bias + col);
            float2 v0, v1;
            v0.x = fmaxf(fmaf(att0, c[mt][nt][0], bv.x), 0.f);
            v0.y = fmaxf(fmaf(att0, c[mt][nt][1], bv.y), 0.f);
            v1.x = fmaxf(fmaf(att1, c[mt][nt][2], bv.x), 0.f);
            v1.y = fmaxf(fmaf(att1, c[mt][nt][3], bv.y), 0.f);
            *(float2*)(o0 + col) = v0;
            *(float2*)(o1 + col) = v1;
        }
    }
}

// ============================================================
extern "C" void kernel_launch(void* const* d_in, const int* in_sizes, int n_in,
                              void* d_out, int out_size) {
    const float* features = (const float*)d_in[0];   // [8,2048,256]
    const float* adj      = (const float*)d_in[1];   // [8,2048,2048]
    const float* W        = (const float*)d_in[2];   // [256,256]
    const float* bias     = (const float*)d_in[3];   // [256]
    float* out = (float*)d_out;                      // [8,2048,256]

    cudaFuncSetAttribute(k_out_tf32, cudaFuncAttributeMaxDynamicSharedMemorySize, 2 * STAGE);

    k_wh      <<<dim3(HD/64, MTOT/64), 256>>>(features, W);
    k_soft_att<<<BATCH, 256>>>();
    k_out_tf32<<<dim3(HD/64, NNODES/128, BATCH), 256, 2 * STAGE>>>(adj, bias, out);
}